// round 10
// baseline (speedup 1.0000x reference)
#include <cuda_runtime.h>
#include <cstdint>

#define NB 128
#define NV 128000
#define KTOP 20
#define NTHREADS 1024
#define CAP 4096
#define THRESH 3.0f

__device__ __forceinline__ float fast_ex2(float x) {
    float r; asm("ex2.approx.ftz.f32 %0, %1;" : "=f"(r) : "f"(x)); return r;
}
__device__ __forceinline__ float fast_lg2(float x) {
    float r; asm("lg2.approx.ftz.f32 %0, %1;" : "=f"(r) : "f"(x)); return r;
}

// Streaming vec4 load pinned in SASS order (asm volatile).
__device__ __forceinline__ float4 ldg_cs4(const float4* p) {
    float4 v;
    asm volatile("ld.global.cs.v4.f32 {%0,%1,%2,%3}, [%4];"
                 : "=f"(v.x), "=f"(v.y), "=f"(v.z), "=f"(v.w) : "l"(p));
    return v;
}

// Monotone pack: larger value wins; on equal value, SMALLER index wins (jax tie rule).
__device__ __forceinline__ unsigned long long packkey(float v, int idx) {
    unsigned fb = __float_as_uint(v);
    fb = (fb & 0x80000000u) ? ~fb : (fb | 0x80000000u);
    return ((unsigned long long)fb << 32) | (unsigned long long)(~(unsigned)idx);
}

// Accurate -ln(u) for u in (0,1): poly(log1p) near 1, MUFU lg2 elsewhere.
__device__ __forceinline__ float neg_log(float u) {
    float d = u - 1.0f;
    float p = fmaf(d, 0.2f, -0.25f);
    p = fmaf(d, p, 0.333333333f);
    p = fmaf(d, p, -0.5f);
    p = fmaf(d, p, 1.0f);
    float lp = -d * p;                        // -log1p(d), good for d in (-0.16, 0]
    float lm = -0.693147181f * fast_lg2(u);
    return (u > 0.84f) ? lp : lm;
}

__global__ __launch_bounds__(NTHREADS) void sampler_kernel(
    const float* __restrict__ logits,
    const float* __restrict__ temp,
    const float* __restrict__ u,
    float* __restrict__ out)
{
    const int b   = blockIdx.x;
    const int tid = threadIdx.x;

    __shared__ float s_val[CAP];
    __shared__ int   s_idx[CAP];
    __shared__ int   s_cnt;
    __shared__ float s_warp[NTHREADS / 32];
    __shared__ unsigned long long s_gkey;
    __shared__ unsigned long long s_win;
    __shared__ float s_lse;
    __shared__ float s_selval[KTOP];
    __shared__ int   s_selidx[KTOP];

    if (tid == 0) { s_cnt = 0; s_gkey = 0ull; }
    __syncthreads();

    const float t      = temp[b];
    const bool  greedy = (t < 1e-5f);
    const float tt     = greedy ? 1.0f : t;
    const float inv_t  = 1.0f / tt;
    const float c      = inv_t * 1.44269504088896f;
    // e-space top-k threshold: e > te  <=>  logit > THRESH (same exp mapping both sides)
    const float te     = fast_ex2(THRESH * c);
    const float inv_te = 0.9995f / te;          // e > te  =>  e*inv_te > 0.999 - u  (u >= 0)

    const float4* __restrict__ lg4 = (const float4*)(logits + (size_t)b * NV);
    const float4* __restrict__ u4  = (const float4*)(u      + (size_t)b * NV);

    float acc0 = 0.0f, acc1 = 0.0f;
    float best_e  = 0.0f;
    float best_lq = 1.0f;
    int   best_gi = 0;
    float invKc   = 1e30f;    // merged filter scale: max(1.01*best_lq/best_e, inv_te)

    // Exact per-element rare path (runs only inside a fired vec4 group).
    #define RARE(lv, uv, ee, gidx)                                                  \
    {                                                                               \
        if ((lv) > THRESH) {                                                        \
            int p = atomicAdd(&s_cnt, 1);                                           \
            if (p < CAP) { s_val[p] = (lv); s_idx[p] = (gidx); }                    \
        }                                                                           \
        if (fmaf((ee), invKc, (uv)) > 0.999f) {                                     \
            float lq = neg_log(uv);                                                 \
            if ((ee) * best_lq > best_e * lq) {                                     \
                best_e = (ee); best_lq = lq; best_gi = (gidx);                      \
                invKc = fmaxf(1.01f * (lq / (ee)), inv_te);                         \
            }                                                                       \
        }                                                                           \
    }

    // Main path per vec4: 4 FMUL + 4 MUFU + 4 FADD + 4 FFMA + 4 FSETP + 3 OR + 1 branch.
    #define PROC(L, U, goff)                                                        \
    {                                                                               \
        float e0 = fast_ex2(L.x * c), e1 = fast_ex2(L.y * c);                       \
        float e2 = fast_ex2(L.z * c), e3 = fast_ex2(L.w * c);                       \
        acc0 += (e0 + e1); acc1 += (e2 + e3);                                       \
        bool h0 = fmaf(e0, invKc, U.x) > 0.999f;                                    \
        bool h1 = fmaf(e1, invKc, U.y) > 0.999f;                                    \
        bool h2 = fmaf(e2, invKc, U.z) > 0.999f;                                    \
        bool h3 = fmaf(e3, invKc, U.w) > 0.999f;                                    \
        if ((h0 | h1) | (h2 | h3)) {                                                \
            RARE(L.x, U.x, e0, (goff) + 0) RARE(L.y, U.y, e1, (goff) + 1)           \
            RARE(L.z, U.z, e2, (goff) + 2) RARE(L.w, U.w, e3, (goff) + 3)           \
        }                                                                           \
    }

    const int nvec = NV / 4;   // 32000
    int i = tid;
    // 3-deep pinned batches (proven R9 shell); warp-uniform guards.
    for (; i + 2 * NTHREADS < nvec; i += 3 * NTHREADS) {
        float4 L0 = ldg_cs4(lg4 + i);
        float4 U0 = ldg_cs4(u4  + i);
        float4 L1 = ldg_cs4(lg4 + i + NTHREADS);
        float4 U1 = ldg_cs4(u4  + i + NTHREADS);
        float4 L2 = ldg_cs4(lg4 + i + 2 * NTHREADS);
        float4 U2 = ldg_cs4(u4  + i + 2 * NTHREADS);

        PROC(L0, U0, 4 * i)
        PROC(L1, U1, 4 * (i + NTHREADS))
        PROC(L2, U2, 4 * (i + 2 * NTHREADS))
    }
    for (; i < nvec; i += NTHREADS) {   // remainder, 1-deep
        float4 L0 = ldg_cs4(lg4 + i);
        float4 U0 = ldg_cs4(u4  + i);
        PROC(L0, U0, 4 * i)
    }
    #undef PROC
    #undef RARE

    // ---- sumexp reduction ----
    float sumexp = acc0 + acc1;
    #pragma unroll
    for (int o = 16; o; o >>= 1) sumexp += __shfl_down_sync(0xFFFFFFFFu, sumexp, o);
    if ((tid & 31) == 0) s_warp[tid >> 5] = sumexp;

    // ---- Gumbel winner across threads ----
    atomicMax(&s_gkey, packkey(best_e / best_lq, best_gi));
    __syncthreads();

    if (tid == 0) {
        float s = 0.0f;
        #pragma unroll
        for (int w = 0; w < NTHREADS / 32; w++) s += s_warp[w];
        s_lse = 0.693147181f * fast_lg2(s);
    }

    // ---- top-K: single-pass rank selection over shared candidates ----
    const int cnt = s_cnt;
    const bool okc = (cnt >= KTOP) && (cnt <= CAP);
    if (okc) {
        for (int p = tid; p < cnt; p += NTHREADS) {
            float v = s_val[p]; int ix = s_idx[p];
            unsigned long long my = packkey(v, ix);
            int rank = 0;
            for (int j = 0; j < cnt; j++)
                rank += (packkey(s_val[j], s_idx[j]) > my) ? 1 : 0;
            if (rank < KTOP) { s_selval[rank] = v; s_selidx[rank] = ix; }
        }
    } else {
        // robust fallback: 20 rounds of global argmax with exclusion (statistically never)
        unsigned long long bound = 0xFFFFFFFFFFFFFFFFull;
        const float* lrow = logits + (size_t)b * NV;
        for (int r = 0; r < KTOP; r++) {
            __syncthreads();
            if (tid == 0) s_win = 0ull;
            __syncthreads();
            unsigned long long loc = 0ull;
            for (int p = tid; p < NV; p += NTHREADS) {
                unsigned long long k = packkey(lrow[p], p);
                if (k < bound && k > loc) loc = k;
            }
            if (loc) atomicMax(&s_win, loc);
            __syncthreads();
            unsigned long long w = s_win;
            bound = w;
            if (tid == 0) {
                unsigned fb = (unsigned)(w >> 32);
                fb = (fb & 0x80000000u) ? (fb ^ 0x80000000u) : ~fb;
                s_selval[r] = __uint_as_float(fb);
                s_selidx[r] = (int)(~(unsigned)(w & 0xFFFFFFFFull));
            }
        }
    }
    __syncthreads();

    // ---- outputs: [sampled(NB) | topk_logprobs(NB*K) | topk_indices(NB*K)] ----
    if (tid < KTOP) {
        float lp = s_selval[tid] * inv_t - s_lse;
        out[NB + b * KTOP + tid]             = lp;
        out[NB + NB * KTOP + b * KTOP + tid] = (float)s_selidx[tid];
    }
    if (tid == 0) {
        int gi = (int)(~(unsigned)(s_gkey & 0xFFFFFFFFull));
        out[b] = (float)(greedy ? s_selidx[0] : gi);
    }
}

extern "C" void kernel_launch(void* const* d_in, const int* in_sizes, int n_in,
                              void* d_out, int out_size) {
    const float* logits = (const float*)d_in[0];
    const float* temp   = (const float*)d_in[1];
    const float* u      = (const float*)d_in[2];
    (void)in_sizes; (void)n_in; (void)out_size;
    sampler_kernel<<<NB, NTHREADS>>>(logits, temp, u, (float*)d_out);
}

// round 11
// speedup vs baseline: 1.0548x; 1.0548x over previous
#include <cuda_runtime.h>
#include <cstdint>

#define NB 128
#define NV 128000
#define KTOP 20
#define NTHREADS 1024
#define CAP 4096
#define THRESH 3.0f

__device__ __forceinline__ float fast_ex2(float x) {
    float r; asm("ex2.approx.ftz.f32 %0, %1;" : "=f"(r) : "f"(x)); return r;
}
__device__ __forceinline__ float fast_lg2(float x) {
    float r; asm("lg2.approx.ftz.f32 %0, %1;" : "=f"(r) : "f"(x)); return r;
}

// Streaming vec4 load pinned in SASS order (asm volatile): textual placement
// controls issue order, giving us a guaranteed software pipeline.
__device__ __forceinline__ float4 ldg_cs4(const float4* p) {
    float4 v;
    asm volatile("ld.global.cs.v4.f32 {%0,%1,%2,%3}, [%4];"
                 : "=f"(v.x), "=f"(v.y), "=f"(v.z), "=f"(v.w) : "l"(p));
    return v;
}

// Monotone pack: larger value wins; on equal value, SMALLER index wins (jax tie rule).
__device__ __forceinline__ unsigned long long packkey(float v, int idx) {
    unsigned fb = __float_as_uint(v);
    fb = (fb & 0x80000000u) ? ~fb : (fb | 0x80000000u);
    return ((unsigned long long)fb << 32) | (unsigned long long)(~(unsigned)idx);
}

// Accurate -ln(u) for u in (0,1): poly(log1p) near 1, MUFU lg2 elsewhere.
__device__ __forceinline__ float neg_log(float u) {
    float d = u - 1.0f;
    float p = fmaf(d, 0.2f, -0.25f);
    p = fmaf(d, p, 0.333333333f);
    p = fmaf(d, p, -0.5f);
    p = fmaf(d, p, 1.0f);
    float lp = -d * p;                        // -log1p(d), good for d in (-0.16, 0]
    float lm = -0.693147181f * fast_lg2(u);
    return (u > 0.84f) ? lp : lm;
}

__global__ __launch_bounds__(NTHREADS) void sampler_kernel(
    const float* __restrict__ logits,
    const float* __restrict__ temp,
    const float* __restrict__ u,
    float* __restrict__ out)
{
    const int b   = blockIdx.x;
    const int tid = threadIdx.x;

    __shared__ float s_val[CAP];
    __shared__ int   s_idx[CAP];
    __shared__ int   s_cnt;
    __shared__ float s_warp[NTHREADS / 32];
    __shared__ unsigned long long s_gkey;
    __shared__ unsigned long long s_win;
    __shared__ float s_lse;
    __shared__ float s_selval[KTOP];
    __shared__ int   s_selidx[KTOP];

    if (tid == 0) { s_cnt = 0; s_gkey = 0ull; }
    __syncthreads();

    const float t      = temp[b];
    const bool  greedy = (t < 1e-5f);
    const float tt     = greedy ? 1.0f : t;
    const float inv_t  = 1.0f / tt;
    const float c      = inv_t * 1.44269504088896f;

    const float4* __restrict__ lg4 = (const float4*)(logits + (size_t)b * NV);
    const float4* __restrict__ u4  = (const float4*)(u      + (size_t)b * NV);

    float acc0 = 0.0f, acc1 = 0.0f;
    float best_e  = 0.0f;
    float best_lq = 1.0f;
    int   best_gi = 0;
    float invK    = 1e30f;   // tight Gumbel filter (R9 semantics, no te merge)

    #define RARE(lv, uv, ee, gidx)                                                  \
    {                                                                               \
        if ((lv) > THRESH) {                                                        \
            int p = atomicAdd(&s_cnt, 1);                                           \
            if (p < CAP) { s_val[p] = (lv); s_idx[p] = (gidx); }                    \
        }                                                                           \
        if (fmaf((ee), invK, (uv)) > 0.999f) {                                      \
            float lq = neg_log(uv);                                                 \
            if ((ee) * best_lq > best_e * lq) {                                     \
                best_e = (ee); best_lq = lq; best_gi = (gidx);                      \
                invK = 1.01f * (lq / (ee));                                         \
            }                                                                       \
        }                                                                           \
    }
    #define ELEM(lv, uv, ee, gidx)                                                  \
    {                                                                               \
        bool hot = ((lv) > THRESH) | (fmaf((ee), invK, (uv)) > 0.999f);             \
        if (hot) RARE(lv, uv, ee, gidx)                                             \
    }
    #define PROC(L, U, goff)                                                        \
    {                                                                               \
        float e0 = fast_ex2(L.x * c), e1 = fast_ex2(L.y * c);                       \
        float e2 = fast_ex2(L.z * c), e3 = fast_ex2(L.w * c);                       \
        acc0 += (e0 + e1); acc1 += (e2 + e3);                                       \
        ELEM(L.x, U.x, e0, (goff) + 0) ELEM(L.y, U.y, e1, (goff) + 1)               \
        ELEM(L.z, U.z, e2, (goff) + 2) ELEM(L.w, U.w, e3, (goff) + 3)               \
    }

    const int nvec = NV / 4;   // 32000
    // Software-pipelined main loop: batch = 2 vec4-pairs (8 elems / thread / iter).
    // Next batch's 4 LDG.128 are issued BEFORE processing the current batch.
    // All guards warp-uniform: every boundary is a multiple of NTHREADS or 32.
    {
        int i = tid;
        float4 cL0, cU0, cL1, cU1;
        cL0 = ldg_cs4(lg4 + i);
        cU0 = ldg_cs4(u4  + i);
        bool h1 = (i + NTHREADS) < nvec;   // true on first iter for all threads
        if (h1) { cL1 = ldg_cs4(lg4 + i + NTHREADS); cU1 = ldg_cs4(u4 + i + NTHREADS); }

        for (;;) {
            const int nx  = i + 2 * NTHREADS;
            const bool nb0 = nx < nvec;
            const bool nb1 = (nx + NTHREADS) < nvec;
            float4 nL0, nU0, nL1, nU1;
            if (nb0) { nL0 = ldg_cs4(lg4 + nx);            nU0 = ldg_cs4(u4 + nx); }
            if (nb1) { nL1 = ldg_cs4(lg4 + nx + NTHREADS); nU1 = ldg_cs4(u4 + nx + NTHREADS); }

            PROC(cL0, cU0, 4 * i)
            if (h1) PROC(cL1, cU1, 4 * (i + NTHREADS))

            if (!nb0) break;
            cL0 = nL0; cU0 = nU0; cL1 = nL1; cU1 = nU1;
            h1 = nb1; i = nx;
        }
    }
    #undef PROC
    #undef ELEM
    #undef RARE

    // ---- sumexp reduction ----
    float sumexp = acc0 + acc1;
    #pragma unroll
    for (int o = 16; o; o >>= 1) sumexp += __shfl_down_sync(0xFFFFFFFFu, sumexp, o);
    if ((tid & 31) == 0) s_warp[tid >> 5] = sumexp;

    // ---- Gumbel winner across threads ----
    atomicMax(&s_gkey, packkey(best_e / best_lq, best_gi));
    __syncthreads();

    if (tid == 0) {
        float s = 0.0f;
        #pragma unroll
        for (int w = 0; w < NTHREADS / 32; w++) s += s_warp[w];
        s_lse = 0.693147181f * fast_lg2(s);
    }

    // ---- top-K: single-pass rank selection over shared candidates ----
    const int cnt = s_cnt;
    const bool okc = (cnt >= KTOP) && (cnt <= CAP);
    if (okc) {
        for (int p = tid; p < cnt; p += NTHREADS) {
            float v = s_val[p]; int ix = s_idx[p];
            unsigned long long my = packkey(v, ix);
            int rank = 0;
            for (int j = 0; j < cnt; j++)
                rank += (packkey(s_val[j], s_idx[j]) > my) ? 1 : 0;
            if (rank < KTOP) { s_selval[rank] = v; s_selidx[rank] = ix; }
        }
    } else {
        // robust fallback: 20 rounds of global argmax with exclusion (statistically never)
        unsigned long long bound = 0xFFFFFFFFFFFFFFFFull;
        const float* lrow = logits + (size_t)b * NV;
        for (int r = 0; r < KTOP; r++) {
            __syncthreads();
            if (tid == 0) s_win = 0ull;
            __syncthreads();
            unsigned long long loc = 0ull;
            for (int p = tid; p < NV; p += NTHREADS) {
                unsigned long long k = packkey(lrow[p], p);
                if (k < bound && k > loc) loc = k;
            }
            if (loc) atomicMax(&s_win, loc);
            __syncthreads();
            unsigned long long w = s_win;
            bound = w;
            if (tid == 0) {
                unsigned fb = (unsigned)(w >> 32);
                fb = (fb & 0x80000000u) ? (fb ^ 0x80000000u) : ~fb;
                s_selval[r] = __uint_as_float(fb);
                s_selidx[r] = (int)(~(unsigned)(w & 0xFFFFFFFFull));
            }
        }
    }
    __syncthreads();

    // ---- outputs: [sampled(NB) | topk_logprobs(NB*K) | topk_indices(NB*K)] ----
    if (tid < KTOP) {
        float lp = s_selval[tid] * inv_t - s_lse;
        out[NB + b * KTOP + tid]             = lp;
        out[NB + NB * KTOP + b * KTOP + tid] = (float)s_selidx[tid];
    }
    if (tid == 0) {
        int gi = (int)(~(unsigned)(s_gkey & 0xFFFFFFFFull));
        out[b] = (float)(greedy ? s_selidx[0] : gi);
    }
}

extern "C" void kernel_launch(void* const* d_in, const int* in_sizes, int n_in,
                              void* d_out, int out_size) {
    const float* logits = (const float*)d_in[0];
    const float* temp   = (const float*)d_in[1];
    const float* u      = (const float*)d_in[2];
    (void)in_sizes; (void)n_in; (void)out_size;
    sampler_kernel<<<NB, NTHREADS>>>(logits, temp, u, (float*)d_out);
}